// round 5
// baseline (speedup 1.0000x reference)
#include <cuda_runtime.h>
#include <cstdint>

// ---------------- Problem constants ----------------
#define M_ENS 8
#define BATCH 4096
#define OBS_D 64
#define IN_D  96
#define H_D   1024
#define HEAD_N 192    // packed head cols (130 real, padded)

#define OFF_LV_O  (M_ENS * BATCH * OBS_D)
#define OFF_MU_R  (2 * M_ENS * BATCH * OBS_D)
#define OFF_LV_R  (OFF_MU_R + M_ENS * BATCH)

// ---------------- Scratch (static device memory) ----------------
__device__ __align__(256) float g_x[BATCH * IN_D];
__device__ __align__(256) float g_h0[(size_t)M_ENS * BATCH * H_D];
__device__ __align__(256) float g_h1[(size_t)M_ENS * BATCH * H_D];
__device__ __align__(256) float g_wt0[(size_t)M_ENS * H_D * IN_D];   // [m][n][k-perm]
__device__ __align__(256) float g_wt1[(size_t)M_ENS * H_D * H_D];
__device__ __align__(256) float g_wt2[(size_t)M_ENS * H_D * H_D];
__device__ __align__(256) float g_wth[(size_t)M_ENS * HEAD_N * H_D]; // [m][n][k-perm]
__device__ __align__(256) float g_bh[M_ENS * HEAD_N];

// ---------------- helpers ----------------
// in-group-of-8 k permutation: logical pair (t, t+4) lands adjacent -> LDS.64
__host__ __device__ __forceinline__ int kperm(int k) {
    return (k & ~7) | (((k & 3) << 1) | ((k >> 2) & 1));
}
__device__ __forceinline__ float tf32r(float x) {
    uint32_t u;
    asm("cvt.rna.tf32.f32 %0, %1;" : "=r"(u) : "f"(x));
    return __uint_as_float(u);
}
#define CPA(dst, src)  asm volatile("cp.async.cg.shared.global [%0], [%1], 16;" :: "r"(dst), "l"(src))
#define CPA_COMMIT()   asm volatile("cp.async.commit_group;" ::: "memory")
template <int N>
__device__ __forceinline__ void cpa_wait() {
    asm volatile("cp.async.wait_group %0;" :: "n"(N) : "memory");
}
__device__ __forceinline__ uint32_t smem_u32(const void* p) {
    uint32_t a;
    asm("{ .reg .u64 t; cvta.to.shared.u64 t, %1; cvt.u32.u64 %0, t; }" : "=r"(a) : "l"(p));
    return a;
}

__device__ __forceinline__ void mma_tf32(float* c, const uint32_t* a, const uint32_t* b) {
    asm volatile(
        "mma.sync.aligned.m16n8k8.row.col.f32.tf32.tf32.f32 "
        "{%0,%1,%2,%3}, {%4,%5,%6,%7}, {%8,%9}, {%0,%1,%2,%3};"
        : "+f"(c[0]), "+f"(c[1]), "+f"(c[2]), "+f"(c[3])
        : "r"(a[0]), "r"(a[1]), "r"(a[2]), "r"(a[3]), "r"(b[0]), "r"(b[1]));
}

__device__ __forceinline__ float softplusf(float x) {
    return fmaxf(x, 0.f) + log1pf(expf(-fabsf(x)));
}
__device__ __forceinline__ float clampv(float v) {
    v = 0.5f  - softplusf(0.5f - v);
    v = -10.f + softplusf(v + 10.f);
    return v;
}

// ---------------- Prep kernels ----------------
__global__ void concat_round(const float* __restrict__ obs,
                             const float* __restrict__ act,
                             float* __restrict__ x) {
    int idx = blockIdx.x * blockDim.x + threadIdx.x;
    if (idx >= BATCH * IN_D) return;
    int b = idx / IN_D, i = idx - b * IN_D;
    float v = (i < OBS_D) ? obs[b * OBS_D + i] : act[b * 32 + (i - OBS_D)];
    x[b * IN_D + kperm(i)] = tf32r(v);
}

// src [m][K][N] -> dst [m][N][K-perm], rounded to tf32
__global__ void transpose_round(const float* __restrict__ src,
                                float* __restrict__ dst, int K, int N) {
    __shared__ float t[32][33];
    int m = blockIdx.z;
    int k0 = blockIdx.x * 32, n0 = blockIdx.y * 32;
    const float* s = src + (size_t)m * K * N;
    float* d = dst + (size_t)m * K * N;
    int tx = threadIdx.x, ty = threadIdx.y;
#pragma unroll
    for (int dy = 0; dy < 32; dy += 8)
        t[ty + dy][tx] = s[(size_t)(k0 + ty + dy) * N + n0 + tx];
    __syncthreads();
    int pk = k0 + kperm(tx);
#pragma unroll
    for (int dy = 0; dy < 32; dy += 8)
        d[(size_t)(n0 + ty + dy) * K + pk] = tf32r(t[tx][ty + dy]);
}

// Pack heads transposed: wth[m][n][k-perm]
__global__ void pack_heads(const float* __restrict__ Wmu_o, const float* __restrict__ Wmu_r,
                           const float* __restrict__ Wv_o,  const float* __restrict__ Wv_r,
                           const float* __restrict__ bmu_o, const float* __restrict__ bmu_r,
                           const float* __restrict__ bv_o,  const float* __restrict__ bv_r,
                           float* __restrict__ wth, float* __restrict__ bh) {
    int idx = blockIdx.x * blockDim.x + threadIdx.x;
    int total = M_ENS * HEAD_N * H_D;
    if (idx < total) {
        int m = idx / (HEAD_N * H_D);
        int rem = idx - m * (HEAD_N * H_D);
        int n = rem / H_D;
        int k = rem - n * H_D;
        size_t mk = (size_t)m * H_D + k;
        float v = 0.f;
        if (n < 64)        v = Wmu_o[mk * 64 + n];
        else if (n == 64)  v = Wmu_r[mk];
        else if (n < 129)  v = Wv_o[mk * 64 + (n - 65)];
        else if (n == 129) v = Wv_r[mk];
        wth[(size_t)m * (HEAD_N * H_D) + n * H_D + kperm(k)] = tf32r(v);
    }
    if (idx < M_ENS * HEAD_N) {
        int m = idx / HEAD_N, n = idx - m * HEAD_N;
        float v = 0.f;
        if (n < 64)        v = bmu_o[m * 64 + n];
        else if (n == 64)  v = bmu_r[m];
        else if (n < 129)  v = bv_o[m * 64 + n - 65];
        else if (n == 129) v = bv_r[m];
        bh[idx] = v;
    }
}

// ---------------- tf32 mma.sync GEMM (round-3 tiling + kperm LDS.64) ----------------
// C[m] (128 x BN) = A[m][row][k] @ Wt[m][col][k]^T (+bias, +act)
// 256 threads, 8 warps, warp tile WM x WN. 3-stage cp.async, BK=32.
// k storage is PERMUTED (kperm): fragment loads are float2 (LDS.64).
template <int KTOT, int BN, int WM, int WN, bool HEADS>
__global__ __launch_bounds__(256)
void gemm_mma(const float* __restrict__ A, size_t sAm, int ldA,
              const float* __restrict__ Wt, size_t sWm,
              const float* __restrict__ bias, int sBm,
              float* __restrict__ out, size_t sOm, int ldO) {
    constexpr int NKB = KTOT / 32;
    constexpr int WARPS_M = 128 / WM;
    constexpr int MT = WM / 16;
    constexpr int NT = WN / 8;
    constexpr int STAGE_F = (128 + BN) * 36;
    constexpr int A_NB4 = 128 * 8 / 256;
    constexpr int B_NB4 = BN * 8 / 256;

    extern __shared__ float smem[];
    const uint32_t sb = smem_u32(smem);
    const int tid = threadIdx.x;
    const int wid = tid >> 5, lane = tid & 31;
    const int wm = wid % WARPS_M, wn = wid / WARPS_M;
    const int gq = lane >> 2, tq = lane & 3;
    const int m = blockIdx.z;
    const int bm0 = blockIdx.x * 128;
    const int bn0 = blockIdx.y * BN;

    const float* Am  = A + sAm * m;
    const float* Wm  = Wt + sWm * m;
    const float* bm_ = bias + (size_t)sBm * m;

    auto fill = [&](int s, int kb) {
        uint32_t abase = sb + s * STAGE_F * 4;
#pragma unroll
        for (int p = 0; p < A_NB4; p++) {
            int f = tid + p * 256;
            int r = f >> 3, cv = f & 7;
            CPA(abase + r * 144 + cv * 16,
                Am + (size_t)(bm0 + r) * ldA + kb * 32 + cv * 4);
        }
        uint32_t bbase = abase + 128 * 144;
#pragma unroll
        for (int p = 0; p < B_NB4; p++) {
            int f = tid + p * 256;
            int r = f >> 3, cv = f & 7;
            CPA(bbase + r * 144 + cv * 16,
                Wm + (size_t)(bn0 + r) * KTOT + kb * 32 + cv * 4);
        }
        CPA_COMMIT();
    };

    float acc[MT][NT][4];
#pragma unroll
    for (int i = 0; i < MT; i++)
#pragma unroll
        for (int j = 0; j < NT; j++)
#pragma unroll
            for (int q = 0; q < 4; q++) acc[i][j][q] = 0.f;

    fill(0, 0);
    fill(1, 1);

    for (int kb = 0; kb < NKB; kb++) {
        if (kb == NKB - 1) cpa_wait<0>(); else cpa_wait<1>();
        __syncthreads();
        if (kb + 2 < NKB) fill((kb + 2) % 3, kb + 2);

        const float* As = smem + (kb % 3) * STAGE_F;
        const float* Bs = As + 128 * 36;
#pragma unroll
        for (int kk = 0; kk < 4; kk++) {
            int cs = kk * 8 + tq * 2;          // permuted slot of (k=tq, k=tq+4)
            uint32_t afr[MT][4], bfr[NT][2];
#pragma unroll
            for (int mt = 0; mt < MT; mt++) {
                int r = wm * WM + mt * 16 + gq;
                float2 lo = *(const float2*)(As + r * 36 + cs);
                float2 hi = *(const float2*)(As + (r + 8) * 36 + cs);
                afr[mt][0] = __float_as_uint(lo.x);
                afr[mt][2] = __float_as_uint(lo.y);
                afr[mt][1] = __float_as_uint(hi.x);
                afr[mt][3] = __float_as_uint(hi.y);
            }
#pragma unroll
            for (int nt = 0; nt < NT; nt++) {
                int rn = wn * WN + nt * 8 + gq;
                float2 v = *(const float2*)(Bs + rn * 36 + cs);
                bfr[nt][0] = __float_as_uint(v.x);
                bfr[nt][1] = __float_as_uint(v.y);
            }
#pragma unroll
            for (int mt = 0; mt < MT; mt++)
#pragma unroll
                for (int nt = 0; nt < NT; nt++)
                    mma_tf32(acc[mt][nt], afr[mt], bfr[nt]);
        }
    }

    // ---- epilogue (register -> gmem) ----
    // acc q: c0 (row gq, col 2tq) c1 (+1 col) c2 (+8 row) c3 (+8 row, +1 col)
    if (!HEADS) {
        // internal activations: columns written in kperm order for the next layer
        float* om = out + sOm * m;
#pragma unroll
        for (int nt = 0; nt < NT; nt++) {
            int gc0 = bn0 + wn * WN + nt * 8 + tq * 2;
            int pc0 = kperm(gc0), pc1 = kperm(gc0 + 1);
            float bA = bm_[gc0], bB = bm_[gc0 + 1];
#pragma unroll
            for (int mt = 0; mt < MT; mt++) {
                size_t gr = bm0 + wm * WM + mt * 16 + gq;
                om[gr * ldO + pc0]       = tf32r(tanhf(acc[mt][nt][0] + bA));
                om[gr * ldO + pc1]       = tf32r(tanhf(acc[mt][nt][1] + bB));
                om[(gr + 8) * ldO + pc0] = tf32r(tanhf(acc[mt][nt][2] + bA));
                om[(gr + 8) * ldO + pc1] = tf32r(tanhf(acc[mt][nt][3] + bB));
            }
        }
    } else {
#pragma unroll
        for (int nt = 0; nt < NT; nt++) {
#pragma unroll
            for (int q2 = 0; q2 < 2; q2++) {
                int gc = bn0 + wn * WN + nt * 8 + tq * 2 + q2;
                if (gc >= 130) continue;
                float bb = bm_[gc];
#pragma unroll
                for (int mt = 0; mt < MT; mt++) {
#pragma unroll
                    for (int h = 0; h < 2; h++) {
                        int gr = bm0 + wm * WM + mt * 16 + gq + h * 8;
                        float v = acc[mt][nt][h * 2 + q2] + bb;
                        if (gc < 64)
                            out[((size_t)m * BATCH + gr) * 64 + gc] = v;
                        else if (gc == 64)
                            out[OFF_MU_R + (size_t)m * BATCH + gr] = v;
                        else if (gc < 129)
                            out[OFF_LV_O + ((size_t)m * BATCH + gr) * 64 + (gc - 65)] = clampv(v);
                        else
                            out[OFF_LV_R + (size_t)m * BATCH + gr] = clampv(v);
                    }
                }
            }
        }
    }
}

// ---------------- Launch ----------------
extern "C" void kernel_launch(void* const* d_in, const int* in_sizes, int n_in,
                              void* d_out, int out_size) {
    const float* obs   = (const float*)d_in[0];
    const float* act   = (const float*)d_in[1];
    const float* W0    = (const float*)d_in[2];
    const float* b0    = (const float*)d_in[3];
    const float* W1    = (const float*)d_in[4];
    const float* b1    = (const float*)d_in[5];
    const float* W2    = (const float*)d_in[6];
    const float* b2    = (const float*)d_in[7];
    const float* Wmu_o = (const float*)d_in[8];
    const float* bmu_o = (const float*)d_in[9];
    const float* Wmu_r = (const float*)d_in[10];
    const float* bmu_r = (const float*)d_in[11];
    const float* Wv_o  = (const float*)d_in[12];
    const float* bv_o  = (const float*)d_in[13];
    const float* Wv_r  = (const float*)d_in[14];
    const float* bv_r  = (const float*)d_in[15];
    float* out = (float*)d_out;

    float *px, *ph0, *ph1, *pwt0, *pwt1, *pwt2, *pwth, *pbh;
    cudaGetSymbolAddress((void**)&px,   g_x);
    cudaGetSymbolAddress((void**)&ph0,  g_h0);
    cudaGetSymbolAddress((void**)&ph1,  g_h1);
    cudaGetSymbolAddress((void**)&pwt0, g_wt0);
    cudaGetSymbolAddress((void**)&pwt1, g_wt1);
    cudaGetSymbolAddress((void**)&pwt2, g_wt2);
    cudaGetSymbolAddress((void**)&pwth, g_wth);
    cudaGetSymbolAddress((void**)&pbh,  g_bh);

    // Layers: BN=128, warp tile 64x32 (round-3 tiling: 2 CTAs/SM).
    // Heads:  BN=64, warp tile 32x32.
    const int SM_L = 3 * (128 + 128) * 36 * 4;   // 110592 B
    const int SM_H = 3 * (128 + 64) * 36 * 4;    //  82944 B
    cudaFuncSetAttribute((const void*)gemm_mma<IN_D, 128, 64, 32, false>,
                         cudaFuncAttributeMaxDynamicSharedMemorySize, SM_L);
    cudaFuncSetAttribute((const void*)gemm_mma<H_D, 128, 64, 32, false>,
                         cudaFuncAttributeMaxDynamicSharedMemorySize, SM_L);
    cudaFuncSetAttribute((const void*)gemm_mma<H_D, 64, 32, 32, true>,
                         cudaFuncAttributeMaxDynamicSharedMemorySize, SM_H);

    // prep (all internal k-storage is kperm-ed)
    concat_round<<<(BATCH * IN_D + 255) / 256, 256>>>(obs, act, px);
    transpose_round<<<dim3(IN_D / 32, H_D / 32, M_ENS), dim3(32, 8)>>>(W0, pwt0, IN_D, H_D);
    transpose_round<<<dim3(H_D / 32, H_D / 32, M_ENS), dim3(32, 8)>>>(W1, pwt1, H_D, H_D);
    transpose_round<<<dim3(H_D / 32, H_D / 32, M_ENS), dim3(32, 8)>>>(W2, pwt2, H_D, H_D);
    pack_heads<<<(M_ENS * HEAD_N * H_D + 255) / 256, 256>>>(
        Wmu_o, Wmu_r, Wv_o, Wv_r, bmu_o, bmu_r, bv_o, bv_r, pwth, pbh);

    const size_t sH = (size_t)BATCH * H_D;
    dim3 gridL(BATCH / 128, H_D / 128, M_ENS);      // (32,8,8)

    gemm_mma<IN_D, 128, 64, 32, false><<<gridL, 256, SM_L>>>(
        px, 0, IN_D, pwt0, (size_t)H_D * IN_D, b0, H_D, ph0, sH, H_D);
    gemm_mma<H_D, 128, 64, 32, false><<<gridL, 256, SM_L>>>(
        ph0, sH, H_D, pwt1, (size_t)H_D * H_D, b1, H_D, ph1, sH, H_D);
    gemm_mma<H_D, 128, 64, 32, false><<<gridL, 256, SM_L>>>(
        ph1, sH, H_D, pwt2, (size_t)H_D * H_D, b2, H_D, ph0, sH, H_D);

    dim3 gridH(BATCH / 128, HEAD_N / 64, M_ENS);    // (32,3,8)
    gemm_mma<H_D, 64, 32, 32, true><<<gridH, 256, SM_H>>>(
        ph0, sH, H_D, pwth, (size_t)HEAD_N * H_D, pbh, HEAD_N, out, 0, 0);
}

// round 6
// speedup vs baseline: 1.2970x; 1.2970x over previous
#include <cuda_runtime.h>
#include <cstdint>

// ---------------- Problem constants ----------------
#define M_ENS 8
#define BATCH 4096
#define OBS_D 64
#define IN_D  96
#define H_D   1024
#define HEAD_N 192    // packed head cols (130 real, padded)

#define OFF_LV_O  (M_ENS * BATCH * OBS_D)
#define OFF_MU_R  (2 * M_ENS * BATCH * OBS_D)
#define OFF_LV_R  (OFF_MU_R + M_ENS * BATCH)

// ---------------- Scratch (static device memory) ----------------
__device__ __align__(256) float g_x[BATCH * IN_D];
__device__ __align__(256) float g_h0[(size_t)M_ENS * BATCH * H_D];
__device__ __align__(256) float g_h1[(size_t)M_ENS * BATCH * H_D];
__device__ __align__(256) float g_wt0[(size_t)M_ENS * H_D * IN_D];   // [m][n][k-perm]
__device__ __align__(256) float g_wt1[(size_t)M_ENS * H_D * H_D];
__device__ __align__(256) float g_wt2[(size_t)M_ENS * H_D * H_D];
__device__ __align__(256) float g_wth[(size_t)M_ENS * HEAD_N * H_D]; // [m][n][k-perm]
__device__ __align__(256) float g_bh[M_ENS * HEAD_N];

// ---------------- helpers ----------------
// in-group-of-8 k permutation: logical pair (t, t+4) lands adjacent -> LDS.64
__host__ __device__ __forceinline__ int kperm(int k) {
    return (k & ~7) | (((k & 3) << 1) | ((k >> 2) & 1));
}
__device__ __forceinline__ float tf32r(float x) {
    uint32_t u;
    asm("cvt.rna.tf32.f32 %0, %1;" : "=r"(u) : "f"(x));
    return __uint_as_float(u);
}
#define CPA(dst, src)  asm volatile("cp.async.cg.shared.global [%0], [%1], 16;" :: "r"(dst), "l"(src))
#define CPA_COMMIT()   asm volatile("cp.async.commit_group;" ::: "memory")
template <int N>
__device__ __forceinline__ void cpa_wait() {
    asm volatile("cp.async.wait_group %0;" :: "n"(N) : "memory");
}
__device__ __forceinline__ uint32_t smem_u32(const void* p) {
    uint32_t a;
    asm("{ .reg .u64 t; cvta.to.shared.u64 t, %1; cvt.u32.u64 %0, t; }" : "=r"(a) : "l"(p));
    return a;
}

__device__ __forceinline__ void mma_tf32(float* c, const uint32_t* a, const uint32_t* b) {
    asm volatile(
        "mma.sync.aligned.m16n8k8.row.col.f32.tf32.tf32.f32 "
        "{%0,%1,%2,%3}, {%4,%5,%6,%7}, {%8,%9}, {%0,%1,%2,%3};"
        : "+f"(c[0]), "+f"(c[1]), "+f"(c[2]), "+f"(c[3])
        : "r"(a[0]), "r"(a[1]), "r"(a[2]), "r"(a[3]), "r"(b[0]), "r"(b[1]));
}

__device__ __forceinline__ float softplusf(float x) {
    return fmaxf(x, 0.f) + log1pf(expf(-fabsf(x)));
}
__device__ __forceinline__ float clampv(float v) {
    v = 0.5f  - softplusf(0.5f - v);
    v = -10.f + softplusf(v + 10.f);
    return v;
}

// ---------------- Prep kernels (3 launches total) ----------------
// Fused: concat+round x, pack+round head weights/bias
__global__ void prep_fused(const float* __restrict__ obs, const float* __restrict__ act,
                           float* __restrict__ x,
                           const float* __restrict__ Wmu_o, const float* __restrict__ Wmu_r,
                           const float* __restrict__ Wv_o,  const float* __restrict__ Wv_r,
                           const float* __restrict__ bmu_o, const float* __restrict__ bmu_r,
                           const float* __restrict__ bv_o,  const float* __restrict__ bv_r,
                           float* __restrict__ wth, float* __restrict__ bh) {
    int idx = blockIdx.x * blockDim.x + threadIdx.x;
    if (idx < BATCH * IN_D) {
        int b = idx / IN_D, i = idx - b * IN_D;
        float v = (i < OBS_D) ? obs[b * OBS_D + i] : act[b * 32 + (i - OBS_D)];
        x[b * IN_D + kperm(i)] = tf32r(v);
    }
    if (idx < M_ENS * HEAD_N * H_D) {
        int m = idx / (HEAD_N * H_D);
        int rem = idx - m * (HEAD_N * H_D);
        int n = rem / H_D;
        int k = rem - n * H_D;
        size_t mk = (size_t)m * H_D + k;
        float v = 0.f;
        if (n < 64)        v = Wmu_o[mk * 64 + n];
        else if (n == 64)  v = Wmu_r[mk];
        else if (n < 129)  v = Wv_o[mk * 64 + (n - 65)];
        else if (n == 129) v = Wv_r[mk];
        wth[(size_t)m * (HEAD_N * H_D) + n * H_D + kperm(k)] = tf32r(v);
    }
    if (idx < M_ENS * HEAD_N) {
        int m = idx / HEAD_N, n = idx - m * HEAD_N;
        float v = 0.f;
        if (n < 64)        v = bmu_o[m * 64 + n];
        else if (n == 64)  v = bmu_r[m];
        else if (n < 129)  v = bv_o[m * 64 + n - 65];
        else if (n == 129) v = bv_r[m];
        bh[idx] = v;
    }
}

// src [m][K][N] -> dst [m][N][K-perm], rounded to tf32. DUAL selects src/dst pair by z>=8.
template <bool DUAL>
__global__ void transpose_round(const float* __restrict__ srcA, float* __restrict__ dstA,
                                const float* __restrict__ srcB, float* __restrict__ dstB,
                                int K, int N) {
    __shared__ float t[32][33];
    int z = blockIdx.z;
    int m = z & 7;
    const float* src = (DUAL && z >= 8) ? srcB : srcA;
    float* dst = (DUAL && z >= 8) ? dstB : dstA;
    int k0 = blockIdx.x * 32, n0 = blockIdx.y * 32;
    const float* s = src + (size_t)m * K * N;
    float* d = dst + (size_t)m * K * N;
    int tx = threadIdx.x, ty = threadIdx.y;
#pragma unroll
    for (int dy = 0; dy < 32; dy += 8)
        t[ty + dy][tx] = s[(size_t)(k0 + ty + dy) * N + n0 + tx];
    __syncthreads();
    int pk = k0 + kperm(tx);
#pragma unroll
    for (int dy = 0; dy < 32; dy += 8)
        d[(size_t)(n0 + ty + dy) * K + pk] = tf32r(t[tx][ty + dy]);
}

// ---------------- tf32 mma.sync GEMM ----------------
// C[m] (128 x BN) = A[m][row][k] @ Wt[m][col][k]^T (+bias, +act)
// 256 threads, 8 warps, warp tile WM x WN. 3-stage cp.async, BK=32.
// Smem rows are exactly 32 words (128B) with float2-slot XOR swizzle
//   word = r*32 + (cs ^ ((r&3)<<3))
// -> conflict-free LDS.64 fragment loads (bank word = ((kk^gq)<<3)|(tq<<1)).
template <int KTOT, int BN, int WM, int WN, bool HEADS>
__global__ __launch_bounds__(256)
void gemm_mma(const float* __restrict__ A, size_t sAm, int ldA,
              const float* __restrict__ Wt, size_t sWm,
              const float* __restrict__ bias, int sBm,
              float* __restrict__ out, size_t sOm, int ldO) {
    constexpr int NKB = KTOT / 32;
    constexpr int WARPS_M = 128 / WM;
    constexpr int MT = WM / 16;
    constexpr int NT = WN / 8;
    constexpr int STAGE_F = (128 + BN) * 32;
    constexpr int A_NB4 = 128 * 8 / 256;
    constexpr int B_NB4 = BN * 8 / 256;

    extern __shared__ float smem[];
    const uint32_t sb = smem_u32(smem);
    const int tid = threadIdx.x;
    const int wid = tid >> 5, lane = tid & 31;
    const int wm = wid % WARPS_M, wn = wid / WARPS_M;
    const int gq = lane >> 2, tq = lane & 3;
    const int sw = (gq & 3) << 3;          // fragment-load swizzle (r&3 == gq&3 always)
    const int m = blockIdx.z;
    const int bm0 = blockIdx.x * 128;
    const int bn0 = blockIdx.y * BN;

    const float* Am  = A + sAm * m;
    const float* Wm  = Wt + sWm * m;
    const float* bm_ = bias + (size_t)sBm * m;

    auto fill = [&](int s, int kb) {
        uint32_t abase = sb + s * STAGE_F * 4;
#pragma unroll
        for (int p = 0; p < A_NB4; p++) {
            int f = tid + p * 256;
            int r = f >> 3, cv = f & 7;
            CPA(abase + r * 128 + ((cv * 16) ^ ((r & 3) << 5)),
                Am + (size_t)(bm0 + r) * ldA + kb * 32 + cv * 4);
        }
        uint32_t bbase = abase + 128 * 128;
#pragma unroll
        for (int p = 0; p < B_NB4; p++) {
            int f = tid + p * 256;
            int r = f >> 3, cv = f & 7;
            CPA(bbase + r * 128 + ((cv * 16) ^ ((r & 3) << 5)),
                Wm + (size_t)(bn0 + r) * KTOT + kb * 32 + cv * 4);
        }
        CPA_COMMIT();
    };

    float acc[MT][NT][4];
#pragma unroll
    for (int i = 0; i < MT; i++)
#pragma unroll
        for (int j = 0; j < NT; j++)
#pragma unroll
            for (int q = 0; q < 4; q++) acc[i][j][q] = 0.f;

    fill(0, 0);
    fill(1, 1);

    for (int kb = 0; kb < NKB; kb++) {
        if (kb == NKB - 1) cpa_wait<0>(); else cpa_wait<1>();
        __syncthreads();
        if (kb + 2 < NKB) fill((kb + 2) % 3, kb + 2);

        const float* As = smem + (kb % 3) * STAGE_F;
        const float* Bs = As + 128 * 32;
#pragma unroll
        for (int kk = 0; kk < 4; kk++) {
            int cs = (kk * 8 + tq * 2) ^ sw;   // swizzled word slot of (k=tq, k=tq+4)
            uint32_t afr[MT][4], bfr[NT][2];
#pragma unroll
            for (int mt = 0; mt < MT; mt++) {
                int r = wm * WM + mt * 16 + gq;
                float2 lo = *(const float2*)(As + r * 32 + cs);
                float2 hi = *(const float2*)(As + (r + 8) * 32 + cs);
                afr[mt][0] = __float_as_uint(lo.x);
                afr[mt][2] = __float_as_uint(lo.y);
                afr[mt][1] = __float_as_uint(hi.x);
                afr[mt][3] = __float_as_uint(hi.y);
            }
#pragma unroll
            for (int nt = 0; nt < NT; nt++) {
                int rn = wn * WN + nt * 8 + gq;
                float2 v = *(const float2*)(Bs + rn * 32 + cs);
                bfr[nt][0] = __float_as_uint(v.x);
                bfr[nt][1] = __float_as_uint(v.y);
            }
#pragma unroll
            for (int mt = 0; mt < MT; mt++)
#pragma unroll
                for (int nt = 0; nt < NT; nt++)
                    mma_tf32(acc[mt][nt], afr[mt], bfr[nt]);
        }
    }

    // ---- epilogue (register -> gmem) ----
    // acc q: c0 (row gq, col 2tq) c1 (+1 col) c2 (+8 row) c3 (+8 row, +1 col)
    if (!HEADS) {
        float* om = out + sOm * m;
#pragma unroll
        for (int nt = 0; nt < NT; nt++) {
            int gc0 = bn0 + wn * WN + nt * 8 + tq * 2;
            int pc0 = kperm(gc0), pc1 = kperm(gc0 + 1);
            float bA = bm_[gc0], bB = bm_[gc0 + 1];
#pragma unroll
            for (int mt = 0; mt < MT; mt++) {
                size_t gr = bm0 + wm * WM + mt * 16 + gq;
                om[gr * ldO + pc0]       = tf32r(tanhf(acc[mt][nt][0] + bA));
                om[gr * ldO + pc1]       = tf32r(tanhf(acc[mt][nt][1] + bB));
                om[(gr + 8) * ldO + pc0] = tf32r(tanhf(acc[mt][nt][2] + bA));
                om[(gr + 8) * ldO + pc1] = tf32r(tanhf(acc[mt][nt][3] + bB));
            }
        }
    } else {
#pragma unroll
        for (int nt = 0; nt < NT; nt++) {
#pragma unroll
            for (int q2 = 0; q2 < 2; q2++) {
                int gc = bn0 + wn * WN + nt * 8 + tq * 2 + q2;
                if (gc >= 130) continue;
                float bb = bm_[gc];
#pragma unroll
                for (int mt = 0; mt < MT; mt++) {
#pragma unroll
                    for (int h = 0; h < 2; h++) {
                        int gr = bm0 + wm * WM + mt * 16 + gq + h * 8;
                        float v = acc[mt][nt][h * 2 + q2] + bb;
                        if (gc < 64)
                            out[((size_t)m * BATCH + gr) * 64 + gc] = v;
                        else if (gc == 64)
                            out[OFF_MU_R + (size_t)m * BATCH + gr] = v;
                        else if (gc < 129)
                            out[OFF_LV_O + ((size_t)m * BATCH + gr) * 64 + (gc - 65)] = clampv(v);
                        else
                            out[OFF_LV_R + (size_t)m * BATCH + gr] = clampv(v);
                    }
                }
            }
        }
    }
}

// ---------------- Launch ----------------
extern "C" void kernel_launch(void* const* d_in, const int* in_sizes, int n_in,
                              void* d_out, int out_size) {
    const float* obs   = (const float*)d_in[0];
    const float* act   = (const float*)d_in[1];
    const float* W0    = (const float*)d_in[2];
    const float* b0    = (const float*)d_in[3];
    const float* W1    = (const float*)d_in[4];
    const float* b1    = (const float*)d_in[5];
    const float* W2    = (const float*)d_in[6];
    const float* b2    = (const float*)d_in[7];
    const float* Wmu_o = (const float*)d_in[8];
    const float* bmu_o = (const float*)d_in[9];
    const float* Wmu_r = (const float*)d_in[10];
    const float* bmu_r = (const float*)d_in[11];
    const float* Wv_o  = (const float*)d_in[12];
    const float* bv_o  = (const float*)d_in[13];
    const float* Wv_r  = (const float*)d_in[14];
    const float* bv_r  = (const float*)d_in[15];
    float* out = (float*)d_out;

    float *px, *ph0, *ph1, *pwt0, *pwt1, *pwt2, *pwth, *pbh;
    cudaGetSymbolAddress((void**)&px,   g_x);
    cudaGetSymbolAddress((void**)&ph0,  g_h0);
    cudaGetSymbolAddress((void**)&ph1,  g_h1);
    cudaGetSymbolAddress((void**)&pwt0, g_wt0);
    cudaGetSymbolAddress((void**)&pwt1, g_wt1);
    cudaGetSymbolAddress((void**)&pwt2, g_wt2);
    cudaGetSymbolAddress((void**)&pwth, g_wth);
    cudaGetSymbolAddress((void**)&pbh,  g_bh);

    // Layers: BN=128, warp tile 64x32 (2 CTAs/SM). Heads: BN=64, warp tile 32x32.
    const int SM_L = 3 * (128 + 128) * 32 * 4;   // 98304 B
    const int SM_H = 3 * (128 + 64) * 32 * 4;    // 73728 B
    cudaFuncSetAttribute((const void*)gemm_mma<IN_D, 128, 64, 32, false>,
                         cudaFuncAttributeMaxDynamicSharedMemorySize, SM_L);
    cudaFuncSetAttribute((const void*)gemm_mma<H_D, 128, 64, 32, false>,
                         cudaFuncAttributeMaxDynamicSharedMemorySize, SM_L);
    cudaFuncSetAttribute((const void*)gemm_mma<H_D, 64, 32, 32, true>,
                         cudaFuncAttributeMaxDynamicSharedMemorySize, SM_H);

    // prep: 3 launches (fused concat+pack; W0; W1+W2 merged)
    prep_fused<<<(M_ENS * HEAD_N * H_D + 255) / 256, 256>>>(
        obs, act, px, Wmu_o, Wmu_r, Wv_o, Wv_r, bmu_o, bmu_r, bv_o, bv_r, pwth, pbh);
    transpose_round<false><<<dim3(IN_D / 32, H_D / 32, M_ENS), dim3(32, 8)>>>(
        W0, pwt0, nullptr, nullptr, IN_D, H_D);
    transpose_round<true><<<dim3(H_D / 32, H_D / 32, 2 * M_ENS), dim3(32, 8)>>>(
        W1, pwt1, W2, pwt2, H_D, H_D);

    const size_t sH = (size_t)BATCH * H_D;
    dim3 gridL(BATCH / 128, H_D / 128, M_ENS);      // (32,8,8)

    gemm_mma<IN_D, 128, 64, 32, false><<<gridL, 256, SM_L>>>(
        px, 0, IN_D, pwt0, (size_t)H_D * IN_D, b0, H_D, ph0, sH, H_D);
    gemm_mma<H_D, 128, 64, 32, false><<<gridL, 256, SM_L>>>(
        ph0, sH, H_D, pwt1, (size_t)H_D * H_D, b1, H_D, ph1, sH, H_D);
    gemm_mma<H_D, 128, 64, 32, false><<<gridL, 256, SM_L>>>(
        ph1, sH, H_D, pwt2, (size_t)H_D * H_D, b2, H_D, ph0, sH, H_D);

    dim3 gridH(BATCH / 128, HEAD_N / 64, M_ENS);    // (32,3,8)
    gemm_mma<H_D, 64, 32, 32, true><<<gridH, 256, SM_H>>>(
        ph0, sH, H_D, pwth, (size_t)HEAD_N * H_D, pbh, HEAD_N, out, 0, 0);
}

// round 8
// speedup vs baseline: 1.3281x; 1.0240x over previous
#include <cuda_runtime.h>
#include <cstdint>

// ---------------- Problem constants ----------------
#define M_ENS 8
#define BATCH 4096
#define OBS_D 64
#define IN_D  96
#define H_D   1024
#define HEAD_N 192    // packed head cols (130 real, padded)

#define OFF_LV_O  (M_ENS * BATCH * OBS_D)
#define OFF_MU_R  (2 * M_ENS * BATCH * OBS_D)
#define OFF_LV_R  (OFF_MU_R + M_ENS * BATCH)

// ---------------- Scratch (static device memory) ----------------
__device__ __align__(256) float g_x[BATCH * IN_D];
__device__ __align__(256) float g_h0[(size_t)M_ENS * BATCH * H_D];
__device__ __align__(256) float g_h1[(size_t)M_ENS * BATCH * H_D];
__device__ __align__(256) float g_wt0[(size_t)M_ENS * H_D * IN_D];   // [m][n][k-perm]
__device__ __align__(256) float g_wt1[(size_t)M_ENS * H_D * H_D];
__device__ __align__(256) float g_wt2[(size_t)M_ENS * H_D * H_D];
__device__ __align__(256) float g_wth[(size_t)M_ENS * HEAD_N * H_D]; // [m][n][k-perm]
__device__ __align__(256) float g_bh[M_ENS * HEAD_N];

// ---------------- helpers ----------------
// in-group-of-8 k permutation: logical pair (t, t+4) lands adjacent -> LDS.64
__host__ __device__ __forceinline__ int kperm(int k) {
    return (k & ~7) | (((k & 3) << 1) | ((k >> 2) & 1));
}
__device__ __forceinline__ float tf32r(float x) {
    uint32_t u;
    asm("cvt.rna.tf32.f32 %0, %1;" : "=r"(u) : "f"(x));
    return __uint_as_float(u);
}
#define CPA(dst, src)  asm volatile("cp.async.cg.shared.global [%0], [%1], 16;" :: "r"(dst), "l"(src))
#define CPA_COMMIT()   asm volatile("cp.async.commit_group;" ::: "memory")
template <int N>
__device__ __forceinline__ void cpa_wait() {
    asm volatile("cp.async.wait_group %0;" :: "n"(N) : "memory");
}
__device__ __forceinline__ uint32_t smem_u32(const void* p) {
    uint32_t a;
    asm("{ .reg .u64 t; cvta.to.shared.u64 t, %1; cvt.u32.u64 %0, t; }" : "=r"(a) : "l"(p));
    return a;
}

__device__ __forceinline__ void mma_tf32(float* c, const uint32_t* a, const uint32_t* b) {
    asm volatile(
        "mma.sync.aligned.m16n8k8.row.col.f32.tf32.tf32.f32 "
        "{%0,%1,%2,%3}, {%4,%5,%6,%7}, {%8,%9}, {%0,%1,%2,%3};"
        : "+f"(c[0]), "+f"(c[1]), "+f"(c[2]), "+f"(c[3])
        : "r"(a[0]), "r"(a[1]), "r"(a[2]), "r"(a[3]), "r"(b[0]), "r"(b[1]));
}

__device__ __forceinline__ float softplusf(float x) {
    return fmaxf(x, 0.f) + log1pf(expf(-fabsf(x)));
}
__device__ __forceinline__ float clampv(float v) {
    v = 0.5f  - softplusf(0.5f - v);
    v = -10.f + softplusf(v + 10.f);
    return v;
}

// ---------------- Prep kernels (3 launches total) ----------------
__global__ void prep_fused(const float* __restrict__ obs, const float* __restrict__ act,
                           float* __restrict__ x,
                           const float* __restrict__ Wmu_o, const float* __restrict__ Wmu_r,
                           const float* __restrict__ Wv_o,  const float* __restrict__ Wv_r,
                           const float* __restrict__ bmu_o, const float* __restrict__ bmu_r,
                           const float* __restrict__ bv_o,  const float* __restrict__ bv_r,
                           float* __restrict__ wth, float* __restrict__ bh) {
    int idx = blockIdx.x * blockDim.x + threadIdx.x;
    if (idx < BATCH * IN_D) {
        int b = idx / IN_D, i = idx - b * IN_D;
        float v = (i < OBS_D) ? obs[b * OBS_D + i] : act[b * 32 + (i - OBS_D)];
        x[b * IN_D + kperm(i)] = tf32r(v);
    }
    if (idx < M_ENS * HEAD_N * H_D) {
        int m = idx / (HEAD_N * H_D);
        int rem = idx - m * (HEAD_N * H_D);
        int n = rem / H_D;
        int k = rem - n * H_D;
        size_t mk = (size_t)m * H_D + k;
        float v = 0.f;
        if (n < 64)        v = Wmu_o[mk * 64 + n];
        else if (n == 64)  v = Wmu_r[mk];
        else if (n < 129)  v = Wv_o[mk * 64 + (n - 65)];
        else if (n == 129) v = Wv_r[mk];
        wth[(size_t)m * (HEAD_N * H_D) + n * H_D + kperm(k)] = tf32r(v);
    }
    if (idx < M_ENS * HEAD_N) {
        int m = idx / HEAD_N, n = idx - m * HEAD_N;
        float v = 0.f;
        if (n < 64)        v = bmu_o[m * 64 + n];
        else if (n == 64)  v = bmu_r[m];
        else if (n < 129)  v = bv_o[m * 64 + n - 65];
        else if (n == 129) v = bv_r[m];
        bh[idx] = v;
    }
}

// src [m][K][N] -> dst [m][N][K-perm], rounded to tf32. DUAL selects pair by z>=8.
template <bool DUAL>
__global__ void transpose_round(const float* __restrict__ srcA, float* __restrict__ dstA,
                                const float* __restrict__ srcB, float* __restrict__ dstB,
                                int K, int N) {
    __shared__ float t[32][33];
    int z = blockIdx.z;
    int m = z & 7;
    const float* src = (DUAL && z >= 8) ? srcB : srcA;
    float* dst = (DUAL && z >= 8) ? dstB : dstA;
    int k0 = blockIdx.x * 32, n0 = blockIdx.y * 32;
    const float* s = src + (size_t)m * K * N;
    float* d = dst + (size_t)m * K * N;
    int tx = threadIdx.x, ty = threadIdx.y;
#pragma unroll
    for (int dy = 0; dy < 32; dy += 8)
        t[ty + dy][tx] = s[(size_t)(k0 + ty + dy) * N + n0 + tx];
    __syncthreads();
    int pk = k0 + kperm(tx);
#pragma unroll
    for (int dy = 0; dy < 32; dy += 8)
        d[(size_t)(n0 + ty + dy) * K + pk] = tf32r(t[tx][ty + dy]);
}

// ---------------- tf32 mma.sync GEMM ----------------
// C[m] (128 x BN) = A[m][row][k] @ Wt[m][col][k]^T (+bias, +act)
// 128 threads / 4 warps as 2 x WARPS_N grid of 64 x WN warp tiles (WN = BN/WARPS_N).
// 3-stage cp.async, BK=32. Rows = 32 words (128B) with float2-slot XOR swizzle:
//   word = r*32 + (cs ^ ((r&3)<<3))  -> conflict-free LDS.64 fragment loads.
template <int KTOT, int BN, int WARPS_N, bool HEADS>
__global__ __launch_bounds__(128)
void gemm_mma(const float* __restrict__ A, size_t sAm, int ldA,
              const float* __restrict__ Wt, size_t sWm,
              const float* __restrict__ bias, int sBm,
              float* __restrict__ out, size_t sOm, int ldO) {
    constexpr int NKB = KTOT / 32;
    constexpr int WN = BN / WARPS_N;
    constexpr int MT = 4;               // WM = 64
    constexpr int NT = WN / 8;
    constexpr int STAGE_F = (128 + BN) * 32;
    constexpr int A_NB4 = 128 * 8 / 128;   // float4 per thread for A tile
    constexpr int B_NB4 = BN * 8 / 128;

    extern __shared__ float smem[];
    const uint32_t sb = smem_u32(smem);
    const int tid = threadIdx.x;
    const int wid = tid >> 5, lane = tid & 31;
    const int wm = wid & 1, wn = wid >> 1;
    const int gq = lane >> 2, tq = lane & 3;
    const int sw = (gq & 3) << 3;          // fragment swizzle (r&3 == gq&3 always)
    const int m = blockIdx.z;
    const int bm0 = blockIdx.x * 128;
    const int bn0 = blockIdx.y * BN;

    const float* Am  = A + sAm * m;
    const float* Wm  = Wt + sWm * m;
    const float* bm_ = bias + (size_t)sBm * m;

    auto fill = [&](int s, int kb) {
        uint32_t abase = sb + s * STAGE_F * 4;
#pragma unroll
        for (int p = 0; p < A_NB4; p++) {
            int f = tid + p * 128;
            int r = f >> 3, cv = f & 7;
            CPA(abase + r * 128 + ((cv * 16) ^ ((r & 3) << 5)),
                Am + (size_t)(bm0 + r) * ldA + kb * 32 + cv * 4);
        }
        uint32_t bbase = abase + 128 * 128;
#pragma unroll
        for (int p = 0; p < B_NB4; p++) {
            int f = tid + p * 128;
            int r = f >> 3, cv = f & 7;
            CPA(bbase + r * 128 + ((cv * 16) ^ ((r & 3) << 5)),
                Wm + (size_t)(bn0 + r) * KTOT + kb * 32 + cv * 4);
        }
        CPA_COMMIT();
    };

    float acc[MT][NT][4];
#pragma unroll
    for (int i = 0; i < MT; i++)
#pragma unroll
        for (int j = 0; j < NT; j++)
#pragma unroll
            for (int q = 0; q < 4; q++) acc[i][j][q] = 0.f;

    fill(0, 0);
    fill(1, 1);

    for (int kb = 0; kb < NKB; kb++) {
        if (kb == NKB - 1) cpa_wait<0>(); else cpa_wait<1>();
        __syncthreads();
        if (kb + 2 < NKB) fill((kb + 2) % 3, kb + 2);

        const float* As = smem + (kb % 3) * STAGE_F;
        const float* Bs = As + 128 * 32;
#pragma unroll
        for (int kk = 0; kk < 4; kk++) {
            int cs = (kk * 8 + tq * 2) ^ sw;   // swizzled slot of (k=tq, k=tq+4)
            uint32_t afr[MT][4], bfr[NT][2];
#pragma unroll
            for (int mt = 0; mt < MT; mt++) {
                int r = wm * 64 + mt * 16 + gq;
                float2 lo = *(const float2*)(As + r * 32 + cs);
                float2 hi = *(const float2*)(As + (r + 8) * 32 + cs);
                afr[mt][0] = __float_as_uint(lo.x);
                afr[mt][2] = __float_as_uint(lo.y);
                afr[mt][1] = __float_as_uint(hi.x);
                afr[mt][3] = __float_as_uint(hi.y);
            }
#pragma unroll
            for (int nt = 0; nt < NT; nt++) {
                int rn = wn * WN + nt * 8 + gq;
                float2 v = *(const float2*)(Bs + rn * 32 + cs);
                bfr[nt][0] = __float_as_uint(v.x);
                bfr[nt][1] = __float_as_uint(v.y);
            }
#pragma unroll
            for (int mt = 0; mt < MT; mt++)
#pragma unroll
                for (int nt = 0; nt < NT; nt++)
                    mma_tf32(acc[mt][nt], afr[mt], bfr[nt]);
        }
    }

    // ---- epilogue (register -> gmem) ----
    // acc q: c0 (row gq, col 2tq) c1 (+1 col) c2 (+8 row) c3 (+8 row, +1 col)
    if (!HEADS) {
        float* om = out + sOm * m;
#pragma unroll
        for (int nt = 0; nt < NT; nt++) {
            int gc0 = bn0 + wn * WN + nt * 8 + tq * 2;
            int pc0 = kperm(gc0), pc1 = kperm(gc0 + 1);
            float bA = bm_[gc0], bB = bm_[gc0 + 1];
#pragma unroll
            for (int mt = 0; mt < MT; mt++) {
                size_t gr = bm0 + wm * 64 + mt * 16 + gq;
                om[gr * ldO + pc0]       = tf32r(tanhf(acc[mt][nt][0] + bA));
                om[gr * ldO + pc1]       = tf32r(tanhf(acc[mt][nt][1] + bB));
                om[(gr + 8) * ldO + pc0] = tf32r(tanhf(acc[mt][nt][2] + bA));
                om[(gr + 8) * ldO + pc1] = tf32r(tanhf(acc[mt][nt][3] + bB));
            }
        }
    } else {
#pragma unroll
        for (int nt = 0; nt < NT; nt++) {
#pragma unroll
            for (int q2 = 0; q2 < 2; q2++) {
                int gc = bn0 + wn * WN + nt * 8 + tq * 2 + q2;
                if (gc >= 130) continue;
                float bb = bm_[gc];
#pragma unroll
                for (int mt = 0; mt < MT; mt++) {
#pragma unroll
                    for (int h = 0; h < 2; h++) {
                        int gr = bm0 + wm * 64 + mt * 16 + gq + h * 8;
                        float v = acc[mt][nt][h * 2 + q2] + bb;
                        if (gc < 64)
                            out[((size_t)m * BATCH + gr) * 64 + gc] = v;
                        else if (gc == 64)
                            out[OFF_MU_R + (size_t)m * BATCH + gr] = v;
                        else if (gc < 129)
                            out[OFF_LV_O + ((size_t)m * BATCH + gr) * 64 + (gc - 65)] = clampv(v);
                        else
                            out[OFF_LV_R + (size_t)m * BATCH + gr] = clampv(v);
                    }
                }
            }
        }
    }
}

// ---------------- Launch ----------------
extern "C" void kernel_launch(void* const* d_in, const int* in_sizes, int n_in,
                              void* d_out, int out_size) {
    const float* obs   = (const float*)d_in[0];
    const float* act   = (const float*)d_in[1];
    const float* W0    = (const float*)d_in[2];
    const float* b0    = (const float*)d_in[3];
    const float* W1    = (const float*)d_in[4];
    const float* b1    = (const float*)d_in[5];
    const float* W2    = (const float*)d_in[6];
    const float* b2    = (const float*)d_in[7];
    const float* Wmu_o = (const float*)d_in[8];
    const float* bmu_o = (const float*)d_in[9];
    const float* Wmu_r = (const float*)d_in[10];
    const float* bmu_r = (const float*)d_in[11];
    const float* Wv_o  = (const float*)d_in[12];
    const float* bv_o  = (const float*)d_in[13];
    const float* Wv_r  = (const float*)d_in[14];
    const float* bv_r  = (const float*)d_in[15];
    float* out = (float*)d_out;

    float *px, *ph0, *ph1, *pwt0, *pwt1, *pwt2, *pwth, *pbh;
    cudaGetSymbolAddress((void**)&px,   g_x);
    cudaGetSymbolAddress((void**)&ph0,  g_h0);
    cudaGetSymbolAddress((void**)&ph1,  g_h1);
    cudaGetSymbolAddress((void**)&pwt0, g_wt0);
    cudaGetSymbolAddress((void**)&pwt1, g_wt1);
    cudaGetSymbolAddress((void**)&pwt2, g_wt2);
    cudaGetSymbolAddress((void**)&pwth, g_wth);
    cudaGetSymbolAddress((void**)&pbh,  g_bh);

    // Layers: BN=128, 4 warps of 64x64 (2 CTAs/SM). Heads: BN=64, 4 warps of 64x32.
    const int SM_L = 3 * (128 + 128) * 32 * 4;   // 98304 B
    const int SM_H = 3 * (128 + 64) * 32 * 4;    // 73728 B
    cudaFuncSetAttribute((const void*)gemm_mma<IN_D, 128, 2, false>,
                         cudaFuncAttributeMaxDynamicSharedMemorySize, SM_L);
    cudaFuncSetAttribute((const void*)gemm_mma<H_D, 128, 2, false>,
                         cudaFuncAttributeMaxDynamicSharedMemorySize, SM_L);
    cudaFuncSetAttribute((const void*)gemm_mma<H_D, 64, 2, true>,
                         cudaFuncAttributeMaxDynamicSharedMemorySize, SM_H);

    // prep: 3 launches (fused concat+pack; W0; W1+W2 merged)
    prep_fused<<<(M_ENS * HEAD_N * H_D + 255) / 256, 256>>>(
        obs, act, px, Wmu_o, Wmu_r, Wv_o, Wv_r, bmu_o, bmu_r, bv_o, bv_r, pwth, pbh);
    transpose_round<false><<<dim3(IN_D / 32, H_D / 32, M_ENS), dim3(32, 8)>>>(
        W0, pwt0, nullptr, nullptr, IN_D, H_D);
    transpose_round<true><<<dim3(H_D / 32, H_D / 32, 2 * M_ENS), dim3(32, 8)>>>(
        W1, pwt1, W2, pwt2, H_D, H_D);

    const size_t sH = (size_t)BATCH * H_D;
    dim3 gridL(BATCH / 128, H_D / 128, M_ENS);      // (32,8,8)

    gemm_mma<IN_D, 128, 2, false><<<gridL, 128, SM_L>>>(
        px, 0, IN_D, pwt0, (size_t)H_D * IN_D, b0, H_D, ph0, sH, H_D);
    gemm_mma<H_D, 128, 2, false><<<gridL, 128, SM_L>>>(
        ph0, sH, H_D, pwt1, (size_t)H_D * H_D, b1, H_D, ph1, sH, H_D);
    gemm_mma<H_D, 128, 2, false><<<gridL, 128, SM_L>>>(
        ph1, sH, H_D, pwt2, (size_t)H_D * H_D, b2, H_D, ph0, sH, H_D);

    dim3 gridH(BATCH / 128, HEAD_N / 64, M_ENS);    // (32,3,8)
    gemm_mma<H_D, 64, 2, true><<<gridH, 128, SM_H>>>(
        ph0, sH, H_D, pwth, (size_t)HEAD_N * H_D, pbh, HEAD_N, out, 0, 0);
}